// round 8
// baseline (speedup 1.0000x reference)
#include <cuda_runtime.h>
#include <cstdint>
#include <math.h>

// VectorQuantizer: N=262144 rows, D=256, K=1024 codes.
// out = [quantized_st (67108864 f32), loss, perplexity]
// Bit-exact replication of XLA:CPU reference arithmetic (validated R2):
//   a[n] = sequential fadd of fl(x_i^2), i ascending
//   b[k] = sequential fadd of fl(e_i^2), i ascending
//   c[n,k] = chained fp32 fma over k ascending, single accumulator
//   d = fl(fl(a+b) - fl(2c)); argmin, lowest-index tie-break
//   out = fl(x + fl(q - x))
//
// R7 layout: warp->16 codes (uniform/broadcast LDS for e), lane->4 rows
// (one conflict-free LDS.128 for x), FFMA2 packed as (x,x)*(e_c,e_c+1).
// Crossbar demand drops from 1.5x fma-time to 0.5x -> fma-pipe bound.

#define NROWS   262144
#define DIM     256
#define NCODES  1024
#define BM      128             // rows per CTA
#define PASSC   256             // codes per pass
#define BD      32              // dims per smem stage
#define NTHR    512
#define NPASS   (NCODES / PASSC)    // 4
#define NSPP    (DIM / BD)          // 8 stages per pass
#define NSTAGE  (NPASS * NSPP)      // 32
#define QELEMS  67108864

__device__ float  g_bsq[NCODES];
__device__ int    g_counts[NCODES];
__device__ double g_sqsum;

static __device__ __forceinline__ unsigned long long ffma2(unsigned long long a,
                                                           unsigned long long b,
                                                           unsigned long long c) {
    unsigned long long d;
    asm("fma.rn.f32x2 %0, %1, %2, %3;" : "=l"(d) : "l"(a), "l"(b), "l"(c));
    return d;
}
static __device__ __forceinline__ unsigned long long bcast2(float v) {
    unsigned long long r;
    asm("mov.b64 %0, {%1, %1};" : "=l"(r) : "f"(v));
    return r;
}
static __device__ __forceinline__ float2 unpack2(unsigned long long v) {
    float2 f;
    asm("mov.b64 {%0, %1}, %2;" : "=f"(f.x), "=f"(f.y) : "l"(v));
    return f;
}
// monotone float -> uint key (handles negatives); equal bits preserve ties
static __device__ __forceinline__ unsigned int okey(float s) {
    unsigned int b = __float_as_uint(s);
    return (b & 0x80000000u) ? ~b : (b | 0x80000000u);
}
static __device__ __forceinline__ unsigned long long umin64(unsigned long long a,
                                                            unsigned long long b) {
    return a < b ? a : b;
}

// ---------------- init: one CTA per code; cooperative load, exact chain ----------------
__global__ void vq_init_kernel(const float* __restrict__ cb) {
    __shared__ float row[DIM];
    int k = blockIdx.x;
    int t = threadIdx.x;                 // 64 threads
    const float4* src = (const float4*)(cb + (size_t)k * DIM);
    float4 v = src[t];
    row[t * 4 + 0] = v.x; row[t * 4 + 1] = v.y;
    row[t * 4 + 2] = v.z; row[t * 4 + 3] = v.w;
    __syncthreads();
    if (t == 0) {
        float s = 0.f;
        #pragma unroll 8
        for (int j = 0; j < DIM; ++j) {
            float w = row[j];
            s = __fadd_rn(s, __fmul_rn(w, w));   // strict sequential, j ascending
        }
        g_bsq[k] = s;
        g_counts[k] = 0;
        if (k == 0) g_sqsum = 0.0;
    }
}

// ---------------- main: pipelined GEMM + rounded scoring + argmin + gather + MSE ----------------
__global__ __launch_bounds__(NTHR, 1)
void vq_main_kernel(const float* __restrict__ x, const float* __restrict__ cb,
                    float* __restrict__ out) {
    extern __shared__ float smem[];
    float* xs = smem;                            // [DIM][BM]  transposed x, 128 KB
    float* es = smem + DIM * BM;                 // 2 x [BD][PASSC] double buffer, 64 KB
    float* sa = smem + DIM * BM + 2 * BD * PASSC;// [BM] row sumsq

    const int tid  = threadIdx.x;
    const int lane = tid & 31;
    const int w    = tid >> 5;                   // warp id 0..15
    const int r0   = lane * 4;                   // rows r0..r0+3 for this lane
    const int cbase = w * 16;                    // 16 codes per warp within pass
    const int m0 = blockIdx.x * BM;
    const float* xg = x + (size_t)m0 * DIM;

    // staging role (fixed): code row scode, dim-half sdg (16 dims = 4 float4)
    const int scode = tid & (PASSC - 1);         // 0..255
    const int sdg   = tid >> 8;                  // 0..1

    // Load x tile transposed: xs[d][row]
    for (int i = tid; i < BM * (DIM / 4); i += NTHR) {
        int row = i & (BM - 1);
        int dg  = i >> 7;                        // 0..63
        float4 v = *(const float4*)(xg + (size_t)row * DIM + dg * 4);
        xs[(dg * 4 + 0) * BM + row] = v.x;
        xs[(dg * 4 + 1) * BM + row] = v.y;
        xs[(dg * 4 + 2) * BM + row] = v.z;
        xs[(dg * 4 + 3) * BM + row] = v.w;
    }

    // Prefetch stage 0 (pass 0, dch 0) into registers
    float4 pf[4];
    {
        const float* src = cb + (size_t)scode * DIM + sdg * 16;
        #pragma unroll
        for (int j = 0; j < 4; ++j) pf[j] = *(const float4*)(src + j * 4);
    }

    __syncthreads();   // xs ready

    // STS stage 0 into buffer 0: es[d][code]
    #pragma unroll
    for (int j = 0; j < 4; ++j) {
        int dd = sdg * 16 + j * 4;
        es[(dd + 0) * PASSC + scode] = pf[j].x;
        es[(dd + 1) * PASSC + scode] = pf[j].y;
        es[(dd + 2) * PASSC + scode] = pf[j].z;
        es[(dd + 3) * PASSC + scode] = pf[j].w;
    }

    // a[n]: strict sequential sum of fl(x^2), d ascending
    if (tid < BM) {
        float aa = 0.f;
        for (int d = 0; d < DIM; ++d) {
            float v = xs[d * BM + tid];
            aa = __fadd_rn(aa, __fmul_rn(v, v));
        }
        sa[tid] = aa;
    }
    __syncthreads();   // stage 0 + sa ready

    float ar[4];
    #pragma unroll
    for (int r = 0; r < 4; ++r) ar[r] = sa[r0 + r];

    unsigned long long best[4];
    #pragma unroll
    for (int r = 0; r < 4; ++r) best[r] = 0xFFFFFFFFFFFFFFFFULL;

    unsigned long long acc[4][8];                // [row][codepair], chained fma k ascending

    for (int st = 0; st < NSTAGE; ++st) {
        const int pass = st >> 3;
        const int dch  = st & 7;

        // Prefetch next stage while computing this one
        if (st + 1 < NSTAGE) {
            const int np = (st + 1) >> 3;
            const int nd = (st + 1) & 7;
            const float* src = cb + (size_t)(np * PASSC + scode) * DIM + nd * BD + sdg * 16;
            #pragma unroll
            for (int j = 0; j < 4; ++j) pf[j] = *(const float4*)(src + j * 4);
        }

        if (dch == 0) {
            #pragma unroll
            for (int r = 0; r < 4; ++r)
                #pragma unroll
                for (int j = 0; j < 8; ++j) acc[r][j] = 0ULL;
        }

        const float* xb = xs + dch * BD * BM + r0;
        const float* eb = es + (st & 1) * (BD * PASSC) + cbase;
        #pragma unroll 8
        for (int dl = 0; dl < BD; ++dl) {        // k ascending within stage
            float4 xv = *(const float4*)(xb + dl * BM);        // rows r0..r0+3
            unsigned long long x0 = bcast2(xv.x);
            unsigned long long x1 = bcast2(xv.y);
            unsigned long long x2 = bcast2(xv.z);
            unsigned long long x3 = bcast2(xv.w);
            const float* ep = eb + dl * PASSC;                 // warp-uniform address
            ulonglong2 ea = *(const ulonglong2*)(ep);          // codepairs 0,1
            ulonglong2 eb2 = *(const ulonglong2*)(ep + 4);     // codepairs 2,3
            ulonglong2 ec = *(const ulonglong2*)(ep + 8);      // codepairs 4,5
            ulonglong2 ed = *(const ulonglong2*)(ep + 12);     // codepairs 6,7
#define ROW4(jI, ee) {                                   \
            acc[0][jI] = ffma2(x0, ee, acc[0][jI]);      \
            acc[1][jI] = ffma2(x1, ee, acc[1][jI]);      \
            acc[2][jI] = ffma2(x2, ee, acc[2][jI]);      \
            acc[3][jI] = ffma2(x3, ee, acc[3][jI]); }
            ROW4(0, ea.x)  ROW4(1, ea.y)
            ROW4(2, eb2.x) ROW4(3, eb2.y)
            ROW4(4, ec.x)  ROW4(5, ec.y)
            ROW4(6, ed.x)  ROW4(7, ed.y)
#undef ROW4
        }

        if (dch == 7) {
            // pass epilogue: d = fl(fl(a+b) - fl(2c)); fold into running best
            #pragma unroll
            for (int j = 0; j < 8; ++j) {
                int cg0 = pass * PASSC + cbase + 2 * j;
                int cg1 = cg0 + 1;
                float b20 = g_bsq[cg0];
                float b21 = g_bsq[cg1];
                #pragma unroll
                for (int r = 0; r < 4; ++r) {
                    float2 v = unpack2(acc[r][j]);
                    float s0 = __fsub_rn(__fadd_rn(ar[r], b20), __fmul_rn(2.0f, v.x));
                    float s1 = __fsub_rn(__fadd_rn(ar[r], b21), __fmul_rn(2.0f, v.y));
                    unsigned long long p0 = ((unsigned long long)okey(s0) << 32) | (unsigned)cg0;
                    unsigned long long p1 = ((unsigned long long)okey(s1) << 32) | (unsigned)cg1;
                    best[r] = umin64(best[r], umin64(p0, p1));
                }
            }
        }

        // STS next stage into the idle buffer
        if (st + 1 < NSTAGE) {
            float* dst = es + ((st + 1) & 1) * (BD * PASSC);
            #pragma unroll
            for (int j = 0; j < 4; ++j) {
                int dd = sdg * 16 + j * 4;
                dst[(dd + 0) * PASSC + scode] = pf[j].x;
                dst[(dd + 1) * PASSC + scode] = pf[j].y;
                dst[(dd + 2) * PASSC + scode] = pf[j].z;
                dst[(dd + 3) * PASSC + scode] = pf[j].w;
            }
            __syncthreads();                     // next buffer ready
        }
    }

    // ---- cross-warp argmin reduction (reuse es region: 64 KB scratch) ----
    __syncthreads();
    unsigned long long* red = (unsigned long long*)es;          // [BM][16] = 16 KB
    int*    sidx = (int*)((char*)es + BM * 16 * 8);             // +512 B
    double* dred = (double*)((char*)sidx + 2048);               // +4 KB

    #pragma unroll
    for (int r = 0; r < 4; ++r) red[(r0 + r) * 16 + w] = best[r];
    __syncthreads();
    if (tid < BM) {
        unsigned long long b = red[tid * 16];
        #pragma unroll
        for (int j = 1; j < 16; ++j) b = umin64(b, red[tid * 16 + j]);
        int idx = (int)(b & 0xFFFFFFFFULL);
        sidx[tid] = idx;
        atomicAdd(&g_counts[idx], 1);
    }
    __syncthreads();

    // ---- fused straight-through output + MSE accumulation (coalesced) ----
    double sq = 0.0;
    float* og = out + (size_t)m0 * DIM;
    for (int i = tid; i < BM * DIM; i += NTHR) {
        int row = i >> 8;                        // DIM == 256
        float e = cb[(size_t)sidx[row] * DIM + (i & 255)];
        float xv = xg[i];
        float df = __fsub_rn(e, xv);             // fl(q - x)
        og[i] = __fadd_rn(xv, df);               // fl(x + fl(q - x))
        float s2 = __fmul_rn(df, df);
        sq += (double)s2;
    }
    dred[tid] = sq;
    __syncthreads();
    for (int s = NTHR / 2; s > 0; s >>= 1) {
        if (tid < s) dred[tid] += dred[tid + s];
        __syncthreads();
    }
    if (tid == 0) atomicAdd(&g_sqsum, dred[0]);
}

// ---------------- finalize: loss + perplexity (fp32 combine like reference) ----------------
__global__ void vq_final_kernel(float* __restrict__ out, long long out_size) {
    __shared__ float terms[NCODES];
    int t = threadIdx.x;
    float p = __fdiv_rn((float)g_counts[t], (float)NROWS);
    terms[t] = __fmul_rn(p, logf(__fadd_rn(p, 1e-10f)));
    __syncthreads();
    if (t == 0 && out_size >= (long long)QELEMS + 2) {
        float s = 0.f;
        for (int k = 0; k < NCODES; ++k) s = __fadd_rn(s, terms[k]);
        float m = (float)(g_sqsum / (double)QELEMS);
        out[QELEMS]     = __fadd_rn(m, __fmul_rn(0.25f, m));   // m + 0.25*m
        out[QELEMS + 1] = expf(-s);
    }
}

extern "C" void kernel_launch(void* const* d_in, const int* in_sizes, int n_in,
                              void* d_out, int out_size) {
    const float* x  = (const float*)d_in[0];   // inputs  [8,32,32,32,256]
    const float* cb = (const float*)d_in[1];   // codebook [1024,256]
    float* out = (float*)d_out;

    const int smem_bytes = (DIM * BM + 2 * BD * PASSC + BM) * 4;   // 197120
    cudaFuncSetAttribute(vq_main_kernel,
                         cudaFuncAttributeMaxDynamicSharedMemorySize, smem_bytes);

    vq_init_kernel<<<NCODES, 64>>>(cb);
    vq_main_kernel<<<NROWS / BM, NTHR, smem_bytes>>>(x, cb, out);
    vq_final_kernel<<<1, NCODES>>>(out, (long long)out_size);
}